// round 4
// baseline (speedup 1.0000x reference)
#include <cuda_runtime.h>
#include <stdint.h>

// out[k,l] = sum_j mitchell_mul(x[k,j], weight[l,j]) + bias[l]
// Mitchell multiply == integer add of offset float bit patterns:
//   packed(v) = (sign<<31) | max(bits(|v|) - 0x1FC00000, 0)
//   mitchell(a,b) = reinterpret_float(packed(a) + packed(b))
// (low fields < 2^30 for these inputs -> no carry into the sign bit; signs XOR)

#define NROWS 512
#define MROWS 512
#define KDIM  1024
#define SPLITS 8
#define KC (KDIM / SPLITS)   // 128 k per split
#define BK 32
#define BM 128               // x rows per CTA
#define BN 64                // w rows per CTA
#define PADM (BM + 4)
#define PADN (BN + 4)
#define TM 8                 // thread tile rows
#define TN 4                 // thread tile cols (2 f32x2 pairs)

__device__ float g_Part[SPLITS * NROWS * MROWS];

__device__ __forceinline__ unsigned int pack1(unsigned int b) {
    unsigned int mag = b & 0x7FFFFFFFu;
    unsigned int low = (mag > 0x1FC00000u) ? (mag - 0x1FC00000u) : 0u;
    return (b & 0x80000000u) | low;
}

union PairCvt {
    uint2 u2;
    unsigned long long u64;
    float f[2];
};

__global__ __launch_bounds__(256, 2) void mitchell_mm_kernel(
    const uint4* __restrict__ xq, const uint4* __restrict__ wq) {
    __shared__ unsigned int Xs[BK][PADM];   // [k][row]
    __shared__ unsigned int Ws[BK][PADN];

    const int tid = threadIdx.x;            // 256 threads: 16 x 16
    const int tx = tid & 15;                // col group (TN=4)
    const int ty = tid >> 4;                // row group (TM=8)
    const int rowBase = blockIdx.y * BM;
    const int colBase = blockIdx.x * BN;
    const int kBase   = blockIdx.z * KC;
    const int K4 = KDIM / 4;

    // Packed f32x2 accumulators: [TM][TN/2], each holds 2 adjacent output cols.
    unsigned long long acc2[TM][TN / 2];
#pragma unroll
    for (int i = 0; i < TM; i++)
#pragma unroll
        for (int j = 0; j < TN / 2; j++) acc2[i][j] = 0ULL;

    // Staging: X tile 128x32 = 1024 uint4 (4/thread), W tile 64x32 = 512 uint4 (2/thread).
    const int xrow = tid >> 3;              // 0..31 (+32 per v)
    const int kq   = tid & 7;               // k-quad 0..7

    uint4 px[4], pw[2];
    auto gload = [&](int kk) {
        int gk4 = (kBase + kk) / 4 + kq;
#pragma unroll
        for (int v = 0; v < 4; v++)
            px[v] = xq[(rowBase + xrow + 32 * v) * K4 + gk4];
#pragma unroll
        for (int v = 0; v < 2; v++)
            pw[v] = wq[(colBase + xrow + 32 * v) * K4 + gk4];
    };

    auto sstore = [&]() {
#pragma unroll
        for (int v = 0; v < 4; v++) {
            int r = xrow + 32 * v;
            Xs[kq * 4 + 0][r] = pack1(px[v].x);
            Xs[kq * 4 + 1][r] = pack1(px[v].y);
            Xs[kq * 4 + 2][r] = pack1(px[v].z);
            Xs[kq * 4 + 3][r] = pack1(px[v].w);
        }
#pragma unroll
        for (int v = 0; v < 2; v++) {
            int r = xrow + 32 * v;
            Ws[kq * 4 + 0][r] = pack1(pw[v].x);
            Ws[kq * 4 + 1][r] = pack1(pw[v].y);
            Ws[kq * 4 + 2][r] = pack1(pw[v].z);
            Ws[kq * 4 + 3][r] = pack1(pw[v].w);
        }
    };

    gload(0);

    for (int s = 0; s < KC / BK; s++) {
        sstore();
        __syncthreads();
        if (s + 1 < KC / BK) gload((s + 1) * BK);

#pragma unroll 4
        for (int k = 0; k < BK; k++) {
            uint4 a0 = *reinterpret_cast<const uint4*>(&Xs[k][ty * TM]);
            uint4 a1 = *reinterpret_cast<const uint4*>(&Xs[k][ty * TM + 4]);
            uint4 b0 = *reinterpret_cast<const uint4*>(&Ws[k][tx * TN]);
            unsigned int a[TM] = {a0.x, a0.y, a0.z, a0.w, a1.x, a1.y, a1.z, a1.w};
            unsigned int b[TN] = {b0.x, b0.y, b0.z, b0.w};
#pragma unroll
            for (int i = 0; i < TM; i++) {
#pragma unroll
                for (int j = 0; j < TN / 2; j++) {
                    // Two integer Mitchell sums packed into an aligned 64-bit pair
                    // (plain C so ptxas can coalesce the pair build), then one
                    // dual-lane FADD accumulates both output columns.
                    PairCvt s2;
                    s2.u2.x = a[i] + b[2 * j];
                    s2.u2.y = a[i] + b[2 * j + 1];
                    asm("add.rn.f32x2 %0, %0, %1;"
                        : "+l"(acc2[i][j]) : "l"(s2.u64));
                }
            }
        }
        __syncthreads();
    }

    float* part = g_Part + blockIdx.z * (NROWS * MROWS);
#pragma unroll
    for (int i = 0; i < TM; i++) {
        int r = rowBase + ty * TM + i;
        PairCvt c0, c1;
        c0.u64 = acc2[i][0];
        c1.u64 = acc2[i][1];
        *reinterpret_cast<float4*>(&part[r * MROWS + colBase + tx * TN]) =
            make_float4(c0.f[0], c0.f[1], c1.f[0], c1.f[1]);
    }
}

// 256 CTAs x 256 threads: one float4 column per thread, 8 batched split loads.
__global__ __launch_bounds__(256) void reduce_kernel(
    const float* __restrict__ bias, float* __restrict__ out) {
    int i4 = blockIdx.x * blockDim.x + threadIdx.x;   // 0..65535 float4s

    float4 p[SPLITS];
#pragma unroll
    for (int z = 0; z < SPLITS; z++)
        p[z] = reinterpret_cast<const float4*>(g_Part + z * NROWS * MROWS)[i4];

    float4 s = p[0];
#pragma unroll
    for (int z = 1; z < SPLITS; z++) {
        s.x += p[z].x; s.y += p[z].y; s.z += p[z].z; s.w += p[z].w;
    }
    float4 bv = reinterpret_cast<const float4*>(bias)[i4 & (MROWS / 4 - 1)];
    s.x += bv.x; s.y += bv.y; s.z += bv.z; s.w += bv.w;
    reinterpret_cast<float4*>(out)[i4] = s;
}

extern "C" void kernel_launch(void* const* d_in, const int* in_sizes, int n_in,
                              void* d_out, int out_size) {
    const float* x    = (const float*)d_in[0];
    const float* w    = (const float*)d_in[1];
    const float* bias = (const float*)d_in[2];
    float* out = (float*)d_out;

    dim3 grid(MROWS / BN, NROWS / BM, SPLITS);   // (8,4,8) = 256 CTAs, 2/SM
    mitchell_mm_kernel<<<grid, 256>>>((const uint4*)x, (const uint4*)w);

    reduce_kernel<<<NROWS * MROWS / 4 / 256, 256>>>(bias, out);
}